// round 12
// baseline (speedup 1.0000x reference)
#include <cuda_runtime.h>
#include <math.h>
#include <float.h>

#define NTOT 16384
#define NT2  (2 * NTOT)
#define BB 64
#define NN 256
#define IND 7
#define HID 64
#define OUTD 32
#define EE 524288
#define ADJ 96
#define NEL 65536
#define SPLIT 16
#define SCAT_BLOCKS (2 * EE / 256)
#define LIN1_BLOCKS (NT2 * 16 / 256)

typedef unsigned long long ull;

// ---------------- scratch ----------------
__device__ float g_xl[NT2 * HID];
__device__ float g_xr[NT2 * HID];
__device__ float g_h[NT2 * HID];
__device__ float g_xl2[NT2 * OUTD];
__device__ float g_xr2[NT2 * OUTD];
__device__ float g_ho[NT2 * OUTD];
__device__ int g_cnt[NT2];
__device__ int g_adj[NT2 * ADJ];
__device__ float g_sim[BB * NEL];
__device__ float g_sum[BB], g_sumsq[BB];
__device__ unsigned g_minkey[BB], g_maxkey[BB];
__device__ float g_S[5][BB];
__device__ int g_arr[5][BB];
__device__ int g_is64;

// ---------------- helpers ----------------
__device__ __forceinline__ unsigned f2key(float f) {
    unsigned u = __float_as_uint(f);
    return (u & 0x80000000u) ? ~u : (u | 0x80000000u);
}
__device__ __forceinline__ float key2f(unsigned k) {
    unsigned u = (k & 0x80000000u) ? (k ^ 0x80000000u) : ~k;
    return __uint_as_float(u);
}
__device__ __forceinline__ float sigf(float x) {
    return __fdividef(1.f, 1.f + __expf(-x));
}
__device__ __forceinline__ ull ffma2(ull a, ull b, ull c) {
    ull d;
    asm("fma.rn.f32x2 %0, %1, %2, %3;" : "=l"(d) : "l"(a), "l"(b), "l"(c));
    return d;
}
__device__ __forceinline__ ull bcast2(float x) {
    ull d;
    asm("mov.b64 %0, {%1, %1};" : "=l"(d) : "f"(x));
    return d;
}

// ---------------- setup ----------------
__global__ void setup_kernel(const int* __restrict__ e1w) {
    int t = blockIdx.x * blockDim.x + threadIdx.x;
    if (t < NT2) {
        g_cnt[t] = 1;
        g_adj[t * ADJ] = t;   // self loop first
    }
    if (t < BB) {
        g_sum[t] = 0.f;
        g_sumsq[t] = 0.f;
        g_minkey[t] = 0xFFFFFFFFu;
        g_maxkey[t] = 0u;
#pragma unroll
        for (int u = 0; u < 5; u++) { g_S[u][t] = 0.f; g_arr[u][t] = 0; }
    }
    if (t == 0) {
        int any = 0;
#pragma unroll
        for (int i = 0; i < 64; i++) any |= e1w[2 * i + 1];
        g_is64 = (any == 0) ? 1 : 0;
    }
}

// ---------------- scatter + lin1 fused ----------------
// lin1 part: thread = (node, 4 outputs), float4 W reads + float4 stores.
__global__ void scatlin_kernel(const void* __restrict__ e1, const void* __restrict__ e2,
                               const float* __restrict__ x1, const float* __restrict__ x2,
                               const float* __restrict__ Wl, const float* __restrict__ Wr,
                               const float* __restrict__ bl, const float* __restrict__ br) {
    int gb = blockIdx.x;
    int tid = threadIdx.x;
    if (gb < SCAT_BLOCKS) {
        int e = gb * 256 + tid;
        int side = (e >= EE);
        int le = e - side * EE;
        const void* ep = side ? e2 : e1;
        int src, dst;
        if (g_is64) {
            const long long* p = (const long long*)ep;
            src = (int)p[le];
            dst = (int)p[EE + le];
        } else {
            const int* p = (const int*)ep;
            src = p[le];
            dst = p[EE + le];
        }
        int n = side * NTOT + dst;
        int pos = atomicAdd(&g_cnt[n], 1);
        if (pos < ADJ) g_adj[n * ADJ + pos] = side * NTOT + src;
    } else {
        int gid = (gb - SCAT_BLOCKS) * 256 + tid;   // over NT2*16
        int n = gid >> 4, dq = gid & 15;            // 4 outputs at dq*4
        const float* x = (n >= NTOT) ? (x2 + (n - NTOT) * IND) : (x1 + n * IND);
        float4 a = *(const float4*)(bl + dq * 4);
        float4 b = *(const float4*)(br + dq * 4);
#pragma unroll
        for (int k = 0; k < IND; k++) {
            float xv = x[k];
            float4 wl = *(const float4*)(Wl + k * HID + dq * 4);
            float4 wr = *(const float4*)(Wr + k * HID + dq * 4);
            a.x = fmaf(xv, wl.x, a.x); a.y = fmaf(xv, wl.y, a.y);
            a.z = fmaf(xv, wl.z, a.z); a.w = fmaf(xv, wl.w, a.w);
            b.x = fmaf(xv, wr.x, b.x); b.y = fmaf(xv, wr.y, b.y);
            b.z = fmaf(xv, wr.z, b.z); b.w = fmaf(xv, wr.w, b.w);
        }
        *(float4*)(g_xl + n * HID + dq * 4) = a;
        *(float4*)(g_xr + n * HID + dq * 4) = b;
    }
}

// ---------------- GATv2: global gather, lane owns 8 elems -----------------
__device__ __forceinline__ float dot8(float4 a0, float4 a1, float4 xr0, float4 xr1,
                                      float4 at0, float4 at1) {
    float zx = a0.x + xr0.x, zy = a0.y + xr0.y, zz = a0.z + xr0.z, zw = a0.w + xr0.w;
    zx = fmaxf(zx, 0.2f * zx); zy = fmaxf(zy, 0.2f * zy);
    zz = fmaxf(zz, 0.2f * zz); zw = fmaxf(zw, 0.2f * zw);
    float p = at0.x * zx;
    p = fmaf(at0.y, zy, p); p = fmaf(at0.z, zz, p); p = fmaf(at0.w, zw, p);
    zx = a1.x + xr1.x; zy = a1.y + xr1.y; zz = a1.z + xr1.z; zw = a1.w + xr1.w;
    zx = fmaxf(zx, 0.2f * zx); zy = fmaxf(zy, 0.2f * zy);
    zz = fmaxf(zz, 0.2f * zz); zw = fmaxf(zw, 0.2f * zw);
    p = fmaf(at1.x, zx, p); p = fmaf(at1.y, zy, p);
    p = fmaf(at1.z, zz, p); p = fmaf(at1.w, zw, p);
    return p;
}

template <int D, int LANES, bool RELU>
__device__ __forceinline__ void gat_body(const float* __restrict__ xl,
                                         const float* __restrict__ xr,
                                         const float* __restrict__ att,
                                         const float* __restrict__ bias,
                                         float* __restrict__ out) {
    constexpr int GP = 32 / LANES;
    int warp = (blockIdx.x * blockDim.x + threadIdx.x) >> 5;
    int lane = threadIdx.x & 31;
    int sub = lane / LANES;
    int l = lane % LANES;
    int n = warp * GP + sub;
    if (n >= NT2) return;
    unsigned gmask = ((1u << LANES) - 1u) << (sub * LANES);

    const float* xlb = xl + l * 8;
    const float* xrb = xr + n * D + l * 8;
    float4 xr0 = *(const float4*)(xrb);
    float4 xr1 = *(const float4*)(xrb + 4);
    float4 at0 = *(const float4*)(att + l * 8);
    float4 at1 = *(const float4*)(att + l * 8 + 4);

    // self loop (score shift reference)
    float4 s0 = *(const float4*)(xlb + n * D);
    float4 s1 = *(const float4*)(xlb + n * D + 4);
    float p = dot8(s0, s1, xr0, xr1, at0, at1);
#pragma unroll
    for (int o = LANES / 2; o > 0; o >>= 1) p += __shfl_xor_sync(gmask, p, o);
    float pself = p;

    float4 accA0 = s0, accA1 = s1; float denA = 1.f;
    float4 accB0 = make_float4(0.f, 0.f, 0.f, 0.f), accB1 = accB0; float denB = 0.f;

    int cnt = g_cnt[n];
    if (cnt > ADJ) cnt = ADJ;
    const int* colp = g_adj + n * ADJ;
    int j = 1;
    for (; j + 1 < cnt; j += 2) {
        int sA = colp[j], sB = colp[j + 1];
        float4 a0 = *(const float4*)(xlb + sA * D);
        float4 a1 = *(const float4*)(xlb + sA * D + 4);
        float4 b0 = *(const float4*)(xlb + sB * D);
        float4 b1 = *(const float4*)(xlb + sB * D + 4);
        float pA = dot8(a0, a1, xr0, xr1, at0, at1);
        float pB = dot8(b0, b1, xr0, xr1, at0, at1);
#pragma unroll
        for (int o = LANES / 2; o > 0; o >>= 1) {
            pA += __shfl_xor_sync(gmask, pA, o);
            pB += __shfl_xor_sync(gmask, pB, o);
        }
        float cA = __expf(pA - pself);
        float cB = __expf(pB - pself);
        denA += cA; denB += cB;
        accA0.x = fmaf(cA, a0.x, accA0.x); accA0.y = fmaf(cA, a0.y, accA0.y);
        accA0.z = fmaf(cA, a0.z, accA0.z); accA0.w = fmaf(cA, a0.w, accA0.w);
        accA1.x = fmaf(cA, a1.x, accA1.x); accA1.y = fmaf(cA, a1.y, accA1.y);
        accA1.z = fmaf(cA, a1.z, accA1.z); accA1.w = fmaf(cA, a1.w, accA1.w);
        accB0.x = fmaf(cB, b0.x, accB0.x); accB0.y = fmaf(cB, b0.y, accB0.y);
        accB0.z = fmaf(cB, b0.z, accB0.z); accB0.w = fmaf(cB, b0.w, accB0.w);
        accB1.x = fmaf(cB, b1.x, accB1.x); accB1.y = fmaf(cB, b1.y, accB1.y);
        accB1.z = fmaf(cB, b1.z, accB1.z); accB1.w = fmaf(cB, b1.w, accB1.w);
    }
    if (j < cnt) {
        int sA = colp[j];
        float4 a0 = *(const float4*)(xlb + sA * D);
        float4 a1 = *(const float4*)(xlb + sA * D + 4);
        float pA = dot8(a0, a1, xr0, xr1, at0, at1);
#pragma unroll
        for (int o = LANES / 2; o > 0; o >>= 1) pA += __shfl_xor_sync(gmask, pA, o);
        float cA = __expf(pA - pself);
        denA += cA;
        accA0.x = fmaf(cA, a0.x, accA0.x); accA0.y = fmaf(cA, a0.y, accA0.y);
        accA0.z = fmaf(cA, a0.z, accA0.z); accA0.w = fmaf(cA, a0.w, accA0.w);
        accA1.x = fmaf(cA, a1.x, accA1.x); accA1.y = fmaf(cA, a1.y, accA1.y);
        accA1.z = fmaf(cA, a1.z, accA1.z); accA1.w = fmaf(cA, a1.w, accA1.w);
    }
    float inv = __fdividef(1.f, denA + denB);
    float4 bi0 = *(const float4*)(bias + l * 8);
    float4 bi1 = *(const float4*)(bias + l * 8 + 4);
    float4 o0, o1;
    o0.x = fmaf(accA0.x + accB0.x, inv, bi0.x);
    o0.y = fmaf(accA0.y + accB0.y, inv, bi0.y);
    o0.z = fmaf(accA0.z + accB0.z, inv, bi0.z);
    o0.w = fmaf(accA0.w + accB0.w, inv, bi0.w);
    o1.x = fmaf(accA1.x + accB1.x, inv, bi1.x);
    o1.y = fmaf(accA1.y + accB1.y, inv, bi1.y);
    o1.z = fmaf(accA1.z + accB1.z, inv, bi1.z);
    o1.w = fmaf(accA1.w + accB1.w, inv, bi1.w);
    if (RELU) {
        o0.x = fmaxf(o0.x, 0.f); o0.y = fmaxf(o0.y, 0.f);
        o0.z = fmaxf(o0.z, 0.f); o0.w = fmaxf(o0.w, 0.f);
        o1.x = fmaxf(o1.x, 0.f); o1.y = fmaxf(o1.y, 0.f);
        o1.z = fmaxf(o1.z, 0.f); o1.w = fmaxf(o1.w, 0.f);
    }
    *(float4*)(out + n * D + l * 8) = o0;
    *(float4*)(out + n * D + l * 8 + 4) = o1;
}

__global__ void gat1_kernel(const float* __restrict__ att, const float* __restrict__ bias) {
    gat_body<HID, 8, true>(g_xl, g_xr, att, bias, g_h);
}
__global__ void gat2_kernel(const float* __restrict__ att, const float* __restrict__ bias) {
    gat_body<OUTD, 4, false>(g_xl2, g_xr2, att, bias, g_ho);
}

// ---------------- layer-2 linear: (node pair, m, 8 outputs), f32x2 --------
// 512 blocks x 256 threads = 131072 threads; FFMA2:LDS = 8:2 per k.
#define WR_OFF 2056   /* Wr offset in floats */
__global__ void __launch_bounds__(256) lin2_kernel(
        const float* __restrict__ Wl, const float* __restrict__ Wr,
        const float* __restrict__ bl, const float* __restrict__ br) {
    __shared__ __align__(16) float sW[WR_OFF + HID * OUTD];
    int tid = threadIdx.x;
    {
        const float4* wl4 = (const float4*)Wl;
        const float4* wr4 = (const float4*)Wr;
#pragma unroll
        for (int i = tid; i < HID * OUTD / 4; i += 256) {
            ((float4*)sW)[i] = wl4[i];
            *(float4*)(sW + WR_OFF + i * 4) = wr4[i];
        }
    }
    __syncthreads();

    int t = blockIdx.x * 256 + tid;
    int oq = t & 3;             // 8-output group
    int m = (t >> 2) & 1;       // 0=l, 1=r
    int npair = t >> 3;
    int n0 = npair * 2;

    const float* W = sW + m * WR_OFF + oq * 8;
    const float* bp = (m ? br : bl) + oq * 8;

    ull a0[4], a1[4];
#pragma unroll
    for (int i = 0; i < 4; i++) {
        ull bv = *(const ull*)(bp + i * 2);
        a0[i] = bv;
        a1[i] = bv;
    }

    const float4* h0 = (const float4*)(g_h + n0 * HID);
    const float4* h1 = (const float4*)(g_h + (n0 + 1) * HID);
#pragma unroll 4
    for (int k4 = 0; k4 < HID / 4; k4++) {
        float4 ha = h0[k4];
        float4 hb = h1[k4];
#pragma unroll
        for (int kk = 0; kk < 4; kk++) {
            float fa = (kk == 0) ? ha.x : (kk == 1) ? ha.y : (kk == 2) ? ha.z : ha.w;
            float fb = (kk == 0) ? hb.x : (kk == 1) ? hb.y : (kk == 2) ? hb.z : hb.w;
            ull hha = bcast2(fa);
            ull hhb = bcast2(fb);
            const float* Wk = W + (k4 * 4 + kk) * OUTD;
            longlong2 w01 = *(const longlong2*)(Wk);      // 4 floats
            longlong2 w23 = *(const longlong2*)(Wk + 4);  // 4 floats
            a0[0] = ffma2(hha, (ull)w01.x, a0[0]); a1[0] = ffma2(hhb, (ull)w01.x, a1[0]);
            a0[1] = ffma2(hha, (ull)w01.y, a0[1]); a1[1] = ffma2(hhb, (ull)w01.y, a1[1]);
            a0[2] = ffma2(hha, (ull)w23.x, a0[2]); a1[2] = ffma2(hhb, (ull)w23.x, a1[2]);
            a0[3] = ffma2(hha, (ull)w23.y, a0[3]); a1[3] = ffma2(hhb, (ull)w23.y, a1[3]);
        }
    }
    float* out0 = (m ? g_xr2 : g_xl2) + n0 * OUTD + oq * 8;
    float* out1 = out0 + OUTD;
#pragma unroll
    for (int i = 0; i < 4; i++) {
        *(ull*)(out0 + i * 2) = a0[i];
        *(ull*)(out1 + i * 2) = a1[i];
    }
}

// ---------------- sim = h1 @ h2^T per batch (64-row tiles) + stats --------
__global__ void sim_kernel() {
    __shared__ __align__(16) float sh[32 * 68];   // [k][nloc] nloc<64, pad 68
    int b = blockIdx.y, tile = blockIdx.x;        // 4 tiles of 64 rows
    int tid = threadIdx.x;
    const float* h1 = g_ho + b * NN * OUTD;
    const float* h2 = g_ho + NTOT * OUTD + b * NN * OUTD;

    for (int idx = tid; idx < 64 * 32; idx += 256) {
        int nloc = idx >> 5, k = idx & 31;
        sh[k * 68 + nloc] = h1[(tile * 64 + nloc) * OUTD + k];
    }
    __syncthreads();

    int m = tid;
    float b2[32];
#pragma unroll
    for (int k = 0; k < 32; k++) b2[k] = h2[m * OUTD + k];

    float fsum = 0.f, fsq = 0.f;
    float lmin = FLT_MAX, lmax = -FLT_MAX;
    float* simb = g_sim + b * NEL;

    for (int g = 0; g < 16; g++) {
        int n0 = g * 4;
        float c0 = 0.f, c1 = 0.f, c2 = 0.f, c3 = 0.f;
#pragma unroll
        for (int k = 0; k < 32; k++) {
            float4 q = *(const float4*)&sh[k * 68 + n0];
            float w = b2[k];
            c0 = fmaf(q.x, w, c0);
            c1 = fmaf(q.y, w, c1);
            c2 = fmaf(q.z, w, c2);
            c3 = fmaf(q.w, w, c3);
        }
        int nn = tile * 64 + n0;
        simb[(nn + 0) * NN + m] = c0;
        simb[(nn + 1) * NN + m] = c1;
        simb[(nn + 2) * NN + m] = c2;
        simb[(nn + 3) * NN + m] = c3;
        fsum += (c0 + c1) + (c2 + c3);
        fsq = fmaf(c0, c0, fsq); fsq = fmaf(c1, c1, fsq);
        fsq = fmaf(c2, c2, fsq); fsq = fmaf(c3, c3, fsq);
        lmin = fminf(lmin, fminf(fminf(c0, c1), fminf(c2, c3)));
        lmax = fmaxf(lmax, fmaxf(fmaxf(c0, c1), fmaxf(c2, c3)));
    }
#pragma unroll
    for (int o = 16; o > 0; o >>= 1) {
        fsum += __shfl_xor_sync(0xffffffffu, fsum, o);
        fsq += __shfl_xor_sync(0xffffffffu, fsq, o);
        lmin = fminf(lmin, __shfl_xor_sync(0xffffffffu, lmin, o));
        lmax = fmaxf(lmax, __shfl_xor_sync(0xffffffffu, lmax, o));
    }
    if ((tid & 31) == 0) {
        atomicAdd(&g_sum[b], fsum);
        atomicAdd(&g_sumsq[b], fsq);
        atomicMin(&g_minkey[b], f2key(lmin));
        atomicMax(&g_maxkey[b], f2key(lmax));
    }
}

// ---------------- fused Sinkhorn: prep + 5 passes + output ----------------
__global__ void sinkhorn_kernel(float* __restrict__ out,
                                const float* __restrict__ gamma,
                                const float* __restrict__ beta) {
    __shared__ float shAC[2];
    __shared__ float shS;
    __shared__ float red[8];
    int b = blockIdx.y, tid = threadIdx.x;
    if (tid == 0) {
        double mu = (double)g_sum[b] / (double)NEL;
        double var = (double)g_sumsq[b] / (double)NEL - mu * mu;
        if (var < 0.0) var = 0.0;
        float r = (float)(1.0 / sqrt(var + 1e-5));
        float sc = gamma[0] * r;
        float off = beta[0] - sc * (float)mu;
        float v1 = sc * key2f(g_minkey[b]) + off;
        float v2 = sc * key2f(g_maxkey[b]) + off;
        float mn = fminf(v1, v2), mx = fmaxf(v1, v2);
        shAC[0] = 2.f * sc;              // TAU = 1
        shAC[1] = 2.f * off - mn - mx;
    }
    __syncthreads();
    float A = shAC[0], C = shAC[1];

    const float4* simv = (const float4*)(g_sim + b * NEL + blockIdx.x * (NEL / SPLIT));
    const float nF = (float)NEL, kF = (float)NN;
    const float logc = logf(kF / (nF - kF));
    float s = 0.f, S = 0.f;

#pragma unroll
    for (int t = 0; t < 5; t++) {
        float xo = C + s;
        float acc = 0.f;
#pragma unroll
        for (int j = tid; j < NEL / SPLIT / 4; j += 256) {
            float4 v = simv[j];
            acc += sigf(fmaf(A, v.x, xo));
            acc += sigf(fmaf(A, v.y, xo));
            acc += sigf(fmaf(A, v.z, xo));
            acc += sigf(fmaf(A, v.w, xo));
        }
#pragma unroll
        for (int o = 16; o > 0; o >>= 1) acc += __shfl_xor_sync(0xffffffffu, acc, o);
        if ((tid & 31) == 0) red[tid >> 5] = acc;
        __syncthreads();
        if (tid == 0) {
            float x = red[0];
#pragma unroll
            for (int w = 1; w < 8; w++) x += red[w];
            atomicAdd(&g_S[t][b], x);
            __threadfence();
            atomicAdd(&g_arr[t][b], 1);
            while (*(volatile int*)&g_arr[t][b] != SPLIT) { }
            __threadfence();
            shS = g_S[t][b];
        }
        __syncthreads();
        S = shS;
        if (t < 4) s += logf((nF - S) / S) + logc;
        __syncthreads();
    }
    float inv = kF / S;
    float xo = C + s;
    size_t base = (size_t)b * NEL + blockIdx.x * (NEL / SPLIT);
    float4* outv = (float4*)(out + base);
#pragma unroll
    for (int j = tid; j < NEL / SPLIT / 4; j += 256) {
        float4 v = simv[j];
        float4 o;
        o.x = fminf(1.f, inv * sigf(fmaf(A, v.x, xo)));
        o.y = fminf(1.f, inv * sigf(fmaf(A, v.y, xo)));
        o.z = fminf(1.f, inv * sigf(fmaf(A, v.z, xo)));
        o.w = fminf(1.f, inv * sigf(fmaf(A, v.w, xo)));
        outv[j] = o;
    }
}

// ---------------- launch ----------------
extern "C" void kernel_launch(void* const* d_in, const int* in_sizes, int n_in,
                              void* d_out, int out_size) {
    const float* x1 = (const float*)d_in[0];
    const float* x2 = (const float*)d_in[1];
    const void* e1 = d_in[2];
    const void* e2 = d_in[3];
    const float* Wl1 = (const float*)d_in[4];
    const float* Wr1 = (const float*)d_in[5];
    const float* bl1 = (const float*)d_in[6];
    const float* br1 = (const float*)d_in[7];
    const float* att1 = (const float*)d_in[8];
    const float* bias1 = (const float*)d_in[9];
    const float* Wl2 = (const float*)d_in[10];
    const float* Wr2 = (const float*)d_in[11];
    const float* bl2 = (const float*)d_in[12];
    const float* br2 = (const float*)d_in[13];
    const float* att2 = (const float*)d_in[14];
    const float* bias2 = (const float*)d_in[15];
    const float* gamma = (const float*)d_in[16];
    const float* beta = (const float*)d_in[17];

    setup_kernel<<<(NT2 + 255) / 256, 256>>>((const int*)e1);
    scatlin_kernel<<<SCAT_BLOCKS + LIN1_BLOCKS, 256>>>(e1, e2, x1, x2, Wl1, Wr1, bl1, br1);
    gat1_kernel<<<NT2 / 4 / 8, 256>>>(att1, bias1);      // GP=4, 8 warps/block
    lin2_kernel<<<NT2 * 8 / 2 / 256, 256>>>(Wl2, Wr2, bl2, br2);  // 512 blocks x 256
    gat2_kernel<<<NT2 / 8 / 8, 256>>>(att2, bias2);      // GP=8, 8 warps/block
    sim_kernel<<<dim3(4, BB), 256>>>();
    sinkhorn_kernel<<<dim3(SPLIT, BB), 256>>>((float*)d_out, gamma, beta);
}

// round 13
// speedup vs baseline: 1.0806x; 1.0806x over previous
#include <cuda_runtime.h>
#include <math.h>
#include <float.h>

#define NTOT 16384
#define NT2  (2 * NTOT)
#define BB 64
#define NN 256
#define IND 7
#define HID 64
#define OUTD 32
#define EE 524288
#define ADJ 96
#define NEL 65536
#define SPLIT 8
#define SCAT_BLOCKS (2 * EE / 256)
#define LIN1_BLOCKS (NT2 * HID / 256)

typedef unsigned long long ull;

// ---------------- scratch ----------------
__device__ float g_xl[NT2 * HID];
__device__ float g_xr[NT2 * HID];
__device__ float g_h[NT2 * HID];
__device__ float g_xl2[NT2 * OUTD];
__device__ float g_xr2[NT2 * OUTD];
__device__ float g_ho[NT2 * OUTD];
__device__ int g_cnt[NT2];
__device__ int g_adj[NT2 * ADJ];
__device__ float g_sim[BB * NEL];
__device__ float g_sum[BB], g_sumsq[BB];
__device__ unsigned g_minkey[BB], g_maxkey[BB];
__device__ float g_S[5][BB];
__device__ int g_arr[5][BB];
__device__ int g_is64;

// ---------------- helpers ----------------
__device__ __forceinline__ unsigned f2key(float f) {
    unsigned u = __float_as_uint(f);
    return (u & 0x80000000u) ? ~u : (u | 0x80000000u);
}
__device__ __forceinline__ float key2f(unsigned k) {
    unsigned u = (k & 0x80000000u) ? (k ^ 0x80000000u) : ~k;
    return __uint_as_float(u);
}
__device__ __forceinline__ float sigf(float x) {
    return __fdividef(1.f, 1.f + __expf(-x));
}
__device__ __forceinline__ ull ffma2(ull a, ull b, ull c) {
    ull d;
    asm("fma.rn.f32x2 %0, %1, %2, %3;" : "=l"(d) : "l"(a), "l"(b), "l"(c));
    return d;
}
__device__ __forceinline__ ull bcast2(float x) {
    ull d;
    asm("mov.b64 %0, {%1, %1};" : "=l"(d) : "f"(x));
    return d;
}

// ---------------- setup ----------------
__global__ void setup_kernel(const int* __restrict__ e1w) {
    int t = blockIdx.x * blockDim.x + threadIdx.x;
    if (t < NT2) {
        g_cnt[t] = 1;
        g_adj[t * ADJ] = t;   // self loop first
    }
    if (t < BB) {
        g_sum[t] = 0.f;
        g_sumsq[t] = 0.f;
        g_minkey[t] = 0xFFFFFFFFu;
        g_maxkey[t] = 0u;
#pragma unroll
        for (int u = 0; u < 5; u++) { g_S[u][t] = 0.f; g_arr[u][t] = 0; }
    }
    if (t == 0) {
        int any = 0;
#pragma unroll
        for (int i = 0; i < 64; i++) any |= e1w[2 * i + 1];
        g_is64 = (any == 0) ? 1 : 0;
    }
}

// ---------------- scatter + lin1 fused (round-7 proven version) -----------
__global__ void scatlin_kernel(const void* __restrict__ e1, const void* __restrict__ e2,
                               const float* __restrict__ x1, const float* __restrict__ x2,
                               const float* __restrict__ Wl, const float* __restrict__ Wr,
                               const float* __restrict__ bl, const float* __restrict__ br) {
    int gb = blockIdx.x;
    int tid = threadIdx.x;
    if (gb < SCAT_BLOCKS) {
        int e = gb * 256 + tid;
        int side = (e >= EE);
        int le = e - side * EE;
        const void* ep = side ? e2 : e1;
        int src, dst;
        if (g_is64) {
            const long long* p = (const long long*)ep;
            src = (int)p[le];
            dst = (int)p[EE + le];
        } else {
            const int* p = (const int*)ep;
            src = p[le];
            dst = p[EE + le];
        }
        int n = side * NTOT + dst;
        int pos = atomicAdd(&g_cnt[n], 1);
        if (pos < ADJ) g_adj[n * ADJ + pos] = side * NTOT + src;
    } else {
        int gid = (gb - SCAT_BLOCKS) * 256 + tid;
        int n = gid >> 6, d = gid & 63;
        const float* x = (n >= NTOT) ? (x2 + (n - NTOT) * IND) : (x1 + n * IND);
        float a = bl[d], b = br[d];
#pragma unroll
        for (int k = 0; k < IND; k++) {
            float xv = x[k];
            a = fmaf(xv, Wl[k * HID + d], a);
            b = fmaf(xv, Wr[k * HID + d], b);
        }
        g_xl[gid] = a;
        g_xr[gid] = b;
    }
}

// ---------------- GATv2: global gather, lane owns 8 elems (round 7) -------
__device__ __forceinline__ float dot8(float4 a0, float4 a1, float4 xr0, float4 xr1,
                                      float4 at0, float4 at1) {
    float zx = a0.x + xr0.x, zy = a0.y + xr0.y, zz = a0.z + xr0.z, zw = a0.w + xr0.w;
    zx = fmaxf(zx, 0.2f * zx); zy = fmaxf(zy, 0.2f * zy);
    zz = fmaxf(zz, 0.2f * zz); zw = fmaxf(zw, 0.2f * zw);
    float p = at0.x * zx;
    p = fmaf(at0.y, zy, p); p = fmaf(at0.z, zz, p); p = fmaf(at0.w, zw, p);
    zx = a1.x + xr1.x; zy = a1.y + xr1.y; zz = a1.z + xr1.z; zw = a1.w + xr1.w;
    zx = fmaxf(zx, 0.2f * zx); zy = fmaxf(zy, 0.2f * zy);
    zz = fmaxf(zz, 0.2f * zz); zw = fmaxf(zw, 0.2f * zw);
    p = fmaf(at1.x, zx, p); p = fmaf(at1.y, zy, p);
    p = fmaf(at1.z, zz, p); p = fmaf(at1.w, zw, p);
    return p;
}

template <int D, int LANES, bool RELU>
__device__ __forceinline__ void gat_body(const float* __restrict__ xl,
                                         const float* __restrict__ xr,
                                         const float* __restrict__ att,
                                         const float* __restrict__ bias,
                                         float* __restrict__ out) {
    constexpr int GP = 32 / LANES;
    int warp = (blockIdx.x * blockDim.x + threadIdx.x) >> 5;
    int lane = threadIdx.x & 31;
    int sub = lane / LANES;
    int l = lane % LANES;
    int n = warp * GP + sub;
    if (n >= NT2) return;
    unsigned gmask = ((1u << LANES) - 1u) << (sub * LANES);

    const float* xlb = xl + l * 8;
    const float* xrb = xr + n * D + l * 8;
    float4 xr0 = *(const float4*)(xrb);
    float4 xr1 = *(const float4*)(xrb + 4);
    float4 at0 = *(const float4*)(att + l * 8);
    float4 at1 = *(const float4*)(att + l * 8 + 4);

    // self loop (score shift reference)
    float4 s0 = *(const float4*)(xlb + n * D);
    float4 s1 = *(const float4*)(xlb + n * D + 4);
    float p = dot8(s0, s1, xr0, xr1, at0, at1);
#pragma unroll
    for (int o = LANES / 2; o > 0; o >>= 1) p += __shfl_xor_sync(gmask, p, o);
    float pself = p;

    float4 accA0 = s0, accA1 = s1; float denA = 1.f;
    float4 accB0 = make_float4(0.f, 0.f, 0.f, 0.f), accB1 = accB0; float denB = 0.f;

    int cnt = g_cnt[n];
    if (cnt > ADJ) cnt = ADJ;
    const int* colp = g_adj + n * ADJ;
    int j = 1;
    for (; j + 1 < cnt; j += 2) {
        int sA = colp[j], sB = colp[j + 1];
        float4 a0 = *(const float4*)(xlb + sA * D);
        float4 a1 = *(const float4*)(xlb + sA * D + 4);
        float4 b0 = *(const float4*)(xlb + sB * D);
        float4 b1 = *(const float4*)(xlb + sB * D + 4);
        float pA = dot8(a0, a1, xr0, xr1, at0, at1);
        float pB = dot8(b0, b1, xr0, xr1, at0, at1);
#pragma unroll
        for (int o = LANES / 2; o > 0; o >>= 1) {
            pA += __shfl_xor_sync(gmask, pA, o);
            pB += __shfl_xor_sync(gmask, pB, o);
        }
        float cA = __expf(pA - pself);
        float cB = __expf(pB - pself);
        denA += cA; denB += cB;
        accA0.x = fmaf(cA, a0.x, accA0.x); accA0.y = fmaf(cA, a0.y, accA0.y);
        accA0.z = fmaf(cA, a0.z, accA0.z); accA0.w = fmaf(cA, a0.w, accA0.w);
        accA1.x = fmaf(cA, a1.x, accA1.x); accA1.y = fmaf(cA, a1.y, accA1.y);
        accA1.z = fmaf(cA, a1.z, accA1.z); accA1.w = fmaf(cA, a1.w, accA1.w);
        accB0.x = fmaf(cB, b0.x, accB0.x); accB0.y = fmaf(cB, b0.y, accB0.y);
        accB0.z = fmaf(cB, b0.z, accB0.z); accB0.w = fmaf(cB, b0.w, accB0.w);
        accB1.x = fmaf(cB, b1.x, accB1.x); accB1.y = fmaf(cB, b1.y, accB1.y);
        accB1.z = fmaf(cB, b1.z, accB1.z); accB1.w = fmaf(cB, b1.w, accB1.w);
    }
    if (j < cnt) {
        int sA = colp[j];
        float4 a0 = *(const float4*)(xlb + sA * D);
        float4 a1 = *(const float4*)(xlb + sA * D + 4);
        float pA = dot8(a0, a1, xr0, xr1, at0, at1);
#pragma unroll
        for (int o = LANES / 2; o > 0; o >>= 1) pA += __shfl_xor_sync(gmask, pA, o);
        float cA = __expf(pA - pself);
        denA += cA;
        accA0.x = fmaf(cA, a0.x, accA0.x); accA0.y = fmaf(cA, a0.y, accA0.y);
        accA0.z = fmaf(cA, a0.z, accA0.z); accA0.w = fmaf(cA, a0.w, accA0.w);
        accA1.x = fmaf(cA, a1.x, accA1.x); accA1.y = fmaf(cA, a1.y, accA1.y);
        accA1.z = fmaf(cA, a1.z, accA1.z); accA1.w = fmaf(cA, a1.w, accA1.w);
    }
    float inv = __fdividef(1.f, denA + denB);
    float4 bi0 = *(const float4*)(bias + l * 8);
    float4 bi1 = *(const float4*)(bias + l * 8 + 4);
    float4 o0, o1;
    o0.x = fmaf(accA0.x + accB0.x, inv, bi0.x);
    o0.y = fmaf(accA0.y + accB0.y, inv, bi0.y);
    o0.z = fmaf(accA0.z + accB0.z, inv, bi0.z);
    o0.w = fmaf(accA0.w + accB0.w, inv, bi0.w);
    o1.x = fmaf(accA1.x + accB1.x, inv, bi1.x);
    o1.y = fmaf(accA1.y + accB1.y, inv, bi1.y);
    o1.z = fmaf(accA1.z + accB1.z, inv, bi1.z);
    o1.w = fmaf(accA1.w + accB1.w, inv, bi1.w);
    if (RELU) {
        o0.x = fmaxf(o0.x, 0.f); o0.y = fmaxf(o0.y, 0.f);
        o0.z = fmaxf(o0.z, 0.f); o0.w = fmaxf(o0.w, 0.f);
        o1.x = fmaxf(o1.x, 0.f); o1.y = fmaxf(o1.y, 0.f);
        o1.z = fmaxf(o1.z, 0.f); o1.w = fmaxf(o1.w, 0.f);
    }
    *(float4*)(out + n * D + l * 8) = o0;
    *(float4*)(out + n * D + l * 8 + 4) = o1;
}

__global__ void gat1_kernel(const float* __restrict__ att, const float* __restrict__ bias) {
    gat_body<HID, 8, true>(g_xl, g_xr, att, bias, g_h);
}
__global__ void gat2_kernel(const float* __restrict__ att, const float* __restrict__ bias) {
    gat_body<OUTD, 4, false>(g_xl2, g_xr2, att, bias, g_ho);
}

// ---------------- layer-2 linear v6: broadcast weights --------------------
// Block 256 thr = 8 warps = 2 node-groups x 2 matrices x 2 output-halves.
// Warp: 32 nodes (one per lane), 16 outputs of one matrix.
// Weights read via broadcast LDS (all lanes same addr); h staged transposed.
#define HT_STRIDE 65
__global__ void __launch_bounds__(256) lin2_kernel(
        const float* __restrict__ Wl, const float* __restrict__ Wr,
        const float* __restrict__ bl, const float* __restrict__ br) {
    __shared__ __align__(16) float sW[2][HID * OUTD];          // 16 KB
    __shared__ __align__(16) float shT[HID * HT_STRIDE];       // 16.6 KB: [k][node0..63]
    int tid = threadIdx.x;
    int nbase = blockIdx.x * 64;

    // stage weights (coalesced float4)
    {
        const float4* wl4 = (const float4*)Wl;
        const float4* wr4 = (const float4*)Wr;
#pragma unroll
        for (int i = tid; i < HID * OUTD / 4; i += 256) {
            ((float4*)sW[0])[i] = wl4[i];
            ((float4*)sW[1])[i] = wr4[i];
        }
    }
    // stage h transposed: read coalesced along k, write shT[k][node]
    {
        const float4* h4 = (const float4*)(g_h + nbase * HID);
#pragma unroll
        for (int i = tid; i < 64 * (HID / 4); i += 256) {
            int node = i >> 4, kq = i & 15;
            float4 v = h4[i];
            shT[(kq * 4 + 0) * HT_STRIDE + node] = v.x;
            shT[(kq * 4 + 1) * HT_STRIDE + node] = v.y;
            shT[(kq * 4 + 2) * HT_STRIDE + node] = v.z;
            shT[(kq * 4 + 3) * HT_STRIDE + node] = v.w;
        }
    }
    __syncthreads();

    int lane = tid & 31, wid = tid >> 5;
    int grp = wid & 1;            // node group (0/1)
    int m = (wid >> 1) & 1;       // matrix (0=l,1=r)
    int half = wid >> 2;          // output half (0/1)
    int node = nbase + grp * 32 + lane;

    const float* Wb = sW[m] + half * 16;
    const float* bp = (m ? br : bl) + half * 16;
    const float* hcol = shT + grp * 32 + lane;

    ull acc[8];
#pragma unroll
    for (int i = 0; i < 8; i++) acc[i] = *(const ull*)(bp + i * 2);

#pragma unroll 8
    for (int k = 0; k < HID; k++) {
        float hv = hcol[k * HT_STRIDE];            // conflict-free LDS.32
        ull h2 = bcast2(hv);
        const float* Wk = Wb + k * OUTD;
        longlong2 wa = *(const longlong2*)(Wk);     // broadcast LDS.128
        longlong2 wb2 = *(const longlong2*)(Wk + 4);
        longlong2 wc = *(const longlong2*)(Wk + 8);
        longlong2 wd = *(const longlong2*)(Wk + 12);
        acc[0] = ffma2(h2, (ull)wa.x, acc[0]);
        acc[1] = ffma2(h2, (ull)wa.y, acc[1]);
        acc[2] = ffma2(h2, (ull)wb2.x, acc[2]);
        acc[3] = ffma2(h2, (ull)wb2.y, acc[3]);
        acc[4] = ffma2(h2, (ull)wc.x, acc[4]);
        acc[5] = ffma2(h2, (ull)wc.y, acc[5]);
        acc[6] = ffma2(h2, (ull)wd.x, acc[6]);
        acc[7] = ffma2(h2, (ull)wd.y, acc[7]);
    }

    float* outp = (m ? g_xr2 : g_xl2) + node * OUTD + half * 16;
#pragma unroll
    for (int i = 0; i < 4; i++) {
        float4 v;
        v.x = __uint_as_float((unsigned)(acc[i * 2]));
        v.y = __uint_as_float((unsigned)(acc[i * 2] >> 32));
        v.z = __uint_as_float((unsigned)(acc[i * 2 + 1]));
        v.w = __uint_as_float((unsigned)(acc[i * 2 + 1] >> 32));
        *(float4*)(outp + i * 4) = v;
    }
}

// ---------------- sim = h1 @ h2^T per batch (64-row tiles) + stats --------
__global__ void sim_kernel() {
    __shared__ __align__(16) float sh[32 * 68];   // [k][nloc] nloc<64, pad 68
    int b = blockIdx.y, tile = blockIdx.x;        // 4 tiles of 64 rows
    int tid = threadIdx.x;
    const float* h1 = g_ho + b * NN * OUTD;
    const float* h2 = g_ho + NTOT * OUTD + b * NN * OUTD;

    for (int idx = tid; idx < 64 * 32; idx += 256) {
        int nloc = idx >> 5, k = idx & 31;
        sh[k * 68 + nloc] = h1[(tile * 64 + nloc) * OUTD + k];
    }
    __syncthreads();

    int m = tid;
    float b2[32];
#pragma unroll
    for (int k = 0; k < 32; k++) b2[k] = h2[m * OUTD + k];

    float fsum = 0.f, fsq = 0.f;
    float lmin = FLT_MAX, lmax = -FLT_MAX;
    float* simb = g_sim + b * NEL;

    for (int g = 0; g < 16; g++) {
        int n0 = g * 4;
        float c0 = 0.f, c1 = 0.f, c2 = 0.f, c3 = 0.f;
#pragma unroll
        for (int k = 0; k < 32; k++) {
            float4 q = *(const float4*)&sh[k * 68 + n0];
            float w = b2[k];
            c0 = fmaf(q.x, w, c0);
            c1 = fmaf(q.y, w, c1);
            c2 = fmaf(q.z, w, c2);
            c3 = fmaf(q.w, w, c3);
        }
        int nn = tile * 64 + n0;
        simb[(nn + 0) * NN + m] = c0;
        simb[(nn + 1) * NN + m] = c1;
        simb[(nn + 2) * NN + m] = c2;
        simb[(nn + 3) * NN + m] = c3;
        fsum += (c0 + c1) + (c2 + c3);
        fsq = fmaf(c0, c0, fsq); fsq = fmaf(c1, c1, fsq);
        fsq = fmaf(c2, c2, fsq); fsq = fmaf(c3, c3, fsq);
        lmin = fminf(lmin, fminf(fminf(c0, c1), fminf(c2, c3)));
        lmax = fmaxf(lmax, fmaxf(fmaxf(c0, c1), fmaxf(c2, c3)));
    }
#pragma unroll
    for (int o = 16; o > 0; o >>= 1) {
        fsum += __shfl_xor_sync(0xffffffffu, fsum, o);
        fsq += __shfl_xor_sync(0xffffffffu, fsq, o);
        lmin = fminf(lmin, __shfl_xor_sync(0xffffffffu, lmin, o));
        lmax = fmaxf(lmax, __shfl_xor_sync(0xffffffffu, lmax, o));
    }
    if ((tid & 31) == 0) {
        atomicAdd(&g_sum[b], fsum);
        atomicAdd(&g_sumsq[b], fsq);
        atomicMin(&g_minkey[b], f2key(lmin));
        atomicMax(&g_maxkey[b], f2key(lmax));
    }
}

// ---------------- fused Sinkhorn: prep + 5 passes + output ----------------
__global__ void sinkhorn_kernel(float* __restrict__ out,
                                const float* __restrict__ gamma,
                                const float* __restrict__ beta) {
    __shared__ float shAC[2];
    __shared__ float shS;
    __shared__ float red[8];
    int b = blockIdx.y, tid = threadIdx.x;
    if (tid == 0) {
        double mu = (double)g_sum[b] / (double)NEL;
        double var = (double)g_sumsq[b] / (double)NEL - mu * mu;
        if (var < 0.0) var = 0.0;
        float r = (float)(1.0 / sqrt(var + 1e-5));
        float sc = gamma[0] * r;
        float off = beta[0] - sc * (float)mu;
        float v1 = sc * key2f(g_minkey[b]) + off;
        float v2 = sc * key2f(g_maxkey[b]) + off;
        float mn = fminf(v1, v2), mx = fmaxf(v1, v2);
        shAC[0] = 2.f * sc;              // TAU = 1
        shAC[1] = 2.f * off - mn - mx;
    }
    __syncthreads();
    float A = shAC[0], C = shAC[1];

    const float4* simv = (const float4*)(g_sim + b * NEL + blockIdx.x * (NEL / SPLIT));
    const float nF = (float)NEL, kF = (float)NN;
    const float logc = logf(kF / (nF - kF));
    float s = 0.f, S = 0.f;

#pragma unroll
    for (int t = 0; t < 5; t++) {
        float xo = C + s;
        float acc = 0.f;
        for (int j = tid; j < NEL / SPLIT / 4; j += 256) {
            float4 v = simv[j];
            acc += sigf(fmaf(A, v.x, xo));
            acc += sigf(fmaf(A, v.y, xo));
            acc += sigf(fmaf(A, v.z, xo));
            acc += sigf(fmaf(A, v.w, xo));
        }
#pragma unroll
        for (int o = 16; o > 0; o >>= 1) acc += __shfl_xor_sync(0xffffffffu, acc, o);
        if ((tid & 31) == 0) red[tid >> 5] = acc;
        __syncthreads();
        if (tid == 0) {
            float x = red[0];
#pragma unroll
            for (int w = 1; w < 8; w++) x += red[w];
            atomicAdd(&g_S[t][b], x);
            __threadfence();
            atomicAdd(&g_arr[t][b], 1);
            while (*(volatile int*)&g_arr[t][b] != SPLIT) { }
            __threadfence();
            shS = g_S[t][b];
        }
        __syncthreads();
        S = shS;
        if (t < 4) s += logf((nF - S) / S) + logc;
        __syncthreads();
    }
    float inv = kF / S;
    float xo = C + s;
    size_t base = (size_t)b * NEL + blockIdx.x * (NEL / SPLIT);
    float4* outv = (float4*)(out + base);
    for (int j = tid; j < NEL / SPLIT / 4; j += 256) {
        float4 v = simv[j];
        float4 o;
        o.x = fminf(1.f, inv * sigf(fmaf(A, v.x, xo)));
        o.y = fminf(1.f, inv * sigf(fmaf(A, v.y, xo)));
        o.z = fminf(1.f, inv * sigf(fmaf(A, v.z, xo)));
        o.w = fminf(1.f, inv * sigf(fmaf(A, v.w, xo)));
        outv[j] = o;
    }
}

// ---------------- launch ----------------
extern "C" void kernel_launch(void* const* d_in, const int* in_sizes, int n_in,
                              void* d_out, int out_size) {
    const float* x1 = (const float*)d_in[0];
    const float* x2 = (const float*)d_in[1];
    const void* e1 = d_in[2];
    const void* e2 = d_in[3];
    const float* Wl1 = (const float*)d_in[4];
    const float* Wr1 = (const float*)d_in[5];
    const float* bl1 = (const float*)d_in[6];
    const float* br1 = (const float*)d_in[7];
    const float* att1 = (const float*)d_in[8];
    const float* bias1 = (const float*)d_in[9];
    const float* Wl2 = (const float*)d_in[10];
    const float* Wr2 = (const float*)d_in[11];
    const float* bl2 = (const float*)d_in[12];
    const float* br2 = (const float*)d_in[13];
    const float* att2 = (const float*)d_in[14];
    const float* bias2 = (const float*)d_in[15];
    const float* gamma = (const float*)d_in[16];
    const float* beta = (const float*)d_in[17];

    setup_kernel<<<(NT2 + 255) / 256, 256>>>((const int*)e1);
    scatlin_kernel<<<SCAT_BLOCKS + LIN1_BLOCKS, 256>>>(e1, e2, x1, x2, Wl1, Wr1, bl1, br1);
    gat1_kernel<<<NT2 / 4 / 8, 256>>>(att1, bias1);      // GP=4, 8 warps/block
    lin2_kernel<<<NT2 / 64, 256>>>(Wl2, Wr2, bl2, br2);  // 512 blocks
    gat2_kernel<<<NT2 / 8 / 8, 256>>>(att2, bias2);      // GP=8, 8 warps/block
    sim_kernel<<<dim3(4, BB), 256>>>();
    sinkhorn_kernel<<<dim3(SPLIT, BB), 256>>>((float*)d_out, gamma, beta);
}